// round 15
// baseline (speedup 1.0000x reference)
#include <cuda_runtime.h>
#include <cuda_bf16.h>

typedef unsigned int u32;
typedef unsigned long long u64;

#define THREADS 256
#define CTAS 128
#define ROWS 32
#define TSTEPS 64
#define KD 192
#define DT 0.01f

#define WPAD1 200   // halves per row for yA / h1 / WB1  (400 B = 16 mod 128 -> ldmatrix conflict-free)
#define WPAD2 136   // halves per row for WB2            (272 B = 16 mod 128)

// ---- smem byte offsets ----
#define SB_YA  0                          // [32][200] bf16 = 12800 B
#define SB_H1  12800                      // [32][200] bf16 = 12800 B
#define SB_WB1 25600                      // [192][200] bf16 = 76800 B (merged cW1 / rW1, n-major)
#define SB_WB2 102400                     // [192][136] bf16 = 52224 B (merged cW2 / rW2)
#define SB_B1  154624                     // [192] f32 merged bias1
#define SB_B2  155392                     // [192] f32 merged bias2
#define SMEM_BYTES 156160

__device__ __forceinline__ u32 smem_u32(const void* p) {
    u32 a;
    asm("{ .reg .u64 t; cvta.to.shared.u64 t, %1; cvt.u32.u64 %0, t; }" : "=r"(a) : "l"(p));
    return a;
}
__device__ __forceinline__ void ldsm4(u32* r, u32 addr) {
    asm volatile("ldmatrix.sync.aligned.m8n8.x4.shared.b16 {%0,%1,%2,%3}, [%4];"
                 : "=r"(r[0]), "=r"(r[1]), "=r"(r[2]), "=r"(r[3]) : "r"(addr));
}
__device__ __forceinline__ void ldsm2(u32* r, u32 addr) {
    asm volatile("ldmatrix.sync.aligned.m8n8.x2.shared.b16 {%0,%1}, [%2];"
                 : "=r"(r[0]), "=r"(r[1]) : "r"(addr));
}
__device__ __forceinline__ void mma16816(float* d, const u32* a, const u32* b) {
    asm volatile(
        "mma.sync.aligned.m16n8k16.row.col.f32.bf16.bf16.f32 "
        "{%0,%1,%2,%3}, {%4,%5,%6,%7}, {%8,%9}, {%0,%1,%2,%3};"
        : "+f"(d[0]), "+f"(d[1]), "+f"(d[2]), "+f"(d[3])
        : "r"(a[0]), "r"(a[1]), "r"(a[2]), "r"(a[3]), "r"(b[0]), "r"(b[1]));
}
__device__ __forceinline__ u32 pkbf(float a, float b) {
    __nv_bfloat162 h = __floats2bfloat162_rn(a, b);
    return *reinterpret_cast<u32*>(&h);
}
__device__ __forceinline__ float relu(float a) { return fmaxf(a, 0.f); }

__global__ __launch_bounds__(THREADS, 1)
void koopman_mma_kernel(const float* __restrict__ x,
                        const float* __restrict__ cW1, const float* __restrict__ cb1,
                        const float* __restrict__ cW2, const float* __restrict__ cb2,
                        const float* __restrict__ rW1, const float* __restrict__ rb1,
                        const float* __restrict__ rW2, const float* __restrict__ rb2,
                        float* __restrict__ out) {
    extern __shared__ char smem[];
    const u32 sbase = smem_u32(smem);
    const int tid = threadIdx.x;
    const int wid = tid >> 5;
    const int lane = tid & 31;

    __nv_bfloat16* WB1 = (__nv_bfloat16*)(smem + SB_WB1);
    __nv_bfloat16* WB2 = (__nv_bfloat16*)(smem + SB_WB2);
    float* sB1 = (float*)(smem + SB_B1);
    float* sB2 = (float*)(smem + SB_B2);
    u32* h1w = (u32*)(smem + SB_H1);
    u32* yAw = (u32*)(smem + SB_YA);

    // ---- pack merged weights (fp32 -> bf16) ----
    for (int i = tid; i < 192 * 192; i += THREADS) {
        int n = i / 192, k = i % 192;
        float v = (n < 128) ? cW1[n * 192 + k] : rW1[(n - 128) * 192 + k];
        WB1[n * WPAD1 + k] = __float2bfloat16(v);
    }
    for (int i = tid; i < 192 * 128; i += THREADS) {
        int n = i / 128, k = i % 128;
        if (n < 128)      WB2[n * WPAD2 + k] = __float2bfloat16(cW2[n * 128 + k]);
        else if (k < 64)  WB2[n * WPAD2 + k] = __float2bfloat16(rW2[(n - 128) * 64 + k]);
    }
    if (tid < 192) {
        sB1[tid] = (tid < 128) ? cb1[tid] : rb1[tid - 128];
        sB2[tid] = (tid < 128) ? cb2[tid] : rb2[tid - 128];
    }

    // ---- warp work assignment: warp = (mt, q); q = column group 0..3 ----
    const int q  = wid & 3;       // column group
    const int mt = wid >> 2;      // m-tile 0..1 (rows mt*16 .. mt*16+15)

    // ---- fragment geometry ----
    const int g = lane >> 3;
    const int rowA = mt * 16 + ((g & 1) << 3) + (lane & 7);   // global row 0..31
    const int colA = (g >> 1) << 3;                            // 0 or 8
    const int rowB = lane & 7;
    const int colB = (g & 1) << 3;

    // complex n-tiles: cols 8q + 32i (i=0..3); real n-tiles: 128 + 8q + 32j (j=0..1)
    int nc[4], nr[2];
#pragma unroll
    for (int i = 0; i < 4; ++i) nc[i] = 8 * q + 32 * i;
#pragma unroll
    for (int j = 0; j < 2; ++j) nr[j] = 128 + 8 * q + 32 * j;

    const int rowBase = blockIdx.x * ROWS;
    const int fr = lane >> 2;                       // fragment row 0..7
    const int fc = 2 * (lane & 3);                  // fragment col offset (even)
    const int r0w = mt * 16 + fr;                   // this thread's first output row

    // ---- register y-state matching D-fragment layout ----
    float yc[4][4], yr[2][4];
#pragma unroll
    for (int i = 0; i < 4; ++i) {
        int p = nc[i] + fc;
        const float* xr = x + (size_t)(rowBase + r0w) * (TSTEPS * KD) + p;
        float2 v0 = *(const float2*)(xr);
        float2 v1 = *(const float2*)(xr + 8 * (TSTEPS * KD));
        yc[i][0] = v0.x; yc[i][1] = v0.y; yc[i][2] = v1.x; yc[i][3] = v1.y;
    }
#pragma unroll
    for (int j = 0; j < 2; ++j) {
        int p = nr[j] + fc;
        const float* xr = x + (size_t)(rowBase + r0w) * (TSTEPS * KD) + p;
        float2 v0 = *(const float2*)(xr);
        float2 v1 = *(const float2*)(xr + 8 * (TSTEPS * KD));
        yr[j][0] = v0.x; yr[j][1] = v0.y; yr[j][2] = v1.x; yr[j][3] = v1.y;
    }
    // initial yA (bf16 A operand)
#pragma unroll
    for (int i = 0; i < 4; ++i) {
        int p = nc[i] + fc;
        yAw[(r0w * WPAD1 + p) >> 1]       = pkbf(yc[i][0], yc[i][1]);
        yAw[((r0w + 8) * WPAD1 + p) >> 1] = pkbf(yc[i][2], yc[i][3]);
    }
#pragma unroll
    for (int j = 0; j < 2; ++j) {
        int p = nr[j] + fc;
        yAw[(r0w * WPAD1 + p) >> 1]       = pkbf(yr[j][0], yr[j][1]);
        yAw[((r0w + 8) * WPAD1 + p) >> 1] = pkbf(yr[j][2], yr[j][3]);
    }
    __syncthreads();

    const u32 yAb  = sbase + SB_YA;
    const u32 h1b  = sbase + SB_H1;
    const u32 wb1b = sbase + SB_WB1;
    const u32 wb2b = sbase + SB_WB2;

    // ---- hoist ALL GEMM1 B (weight) fragments into registers (144 regs) ----
    u32 b1c[4][12][2];
#pragma unroll
    for (int i = 0; i < 4; ++i)
#pragma unroll
        for (int kt = 0; kt < 12; ++kt)
            ldsm2(b1c[i][kt], wb1b + (u32)((nc[i] + rowB) * WPAD1 + kt * 16 + colB) * 2);
    u32 b1r[2][12][2];
#pragma unroll
    for (int j = 0; j < 2; ++j)
#pragma unroll
        for (int kt = 0; kt < 12; ++kt)
            ldsm2(b1r[j][kt], wb1b + (u32)((nr[j] + rowB) * WPAD1 + kt * 16 + colB) * 2);

    float* outBase = out + (size_t)rowBase * TSTEPS * KD;

    for (int t = 0; t < TSTEPS; ++t) {
        // ===== GEMM1: 1 m-tile x 6 n-tiles, K=192, B in registers =====
        float d[4][4], dr[2][4];
#pragma unroll
        for (int i = 0; i < 4; ++i) { d[i][0] = d[i][1] = d[i][2] = d[i][3] = 0.f; }
#pragma unroll
        for (int j = 0; j < 2; ++j) { dr[j][0] = dr[j][1] = dr[j][2] = dr[j][3] = 0.f; }
#pragma unroll
        for (int kt = 0; kt < 12; ++kt) {
            u32 a[4];
            ldsm4(a, yAb + (u32)(rowA * WPAD1 + kt * 16 + colA) * 2);
#pragma unroll
            for (int i = 0; i < 4; ++i) mma16816(d[i], a, b1c[i][kt]);
#pragma unroll
            for (int j = 0; j < 2; ++j) mma16816(dr[j], a, b1r[j][kt]);
        }
        // epilogue 1: bias + relu -> h1 (bf16)
#pragma unroll
        for (int i = 0; i < 4; ++i) {
            int p = nc[i] + fc;
            float2 bb = *(const float2*)(sB1 + p);
            h1w[(r0w * WPAD1 + p) >> 1]       = pkbf(relu(d[i][0] + bb.x), relu(d[i][1] + bb.y));
            h1w[((r0w + 8) * WPAD1 + p) >> 1] = pkbf(relu(d[i][2] + bb.x), relu(d[i][3] + bb.y));
        }
#pragma unroll
        for (int j = 0; j < 2; ++j) {
            int p = nr[j] + fc;
            float2 bb = *(const float2*)(sB1 + p);
            h1w[(r0w * WPAD1 + p) >> 1]       = pkbf(relu(dr[j][0] + bb.x), relu(dr[j][1] + bb.y));
            h1w[((r0w + 8) * WPAD1 + p) >> 1] = pkbf(relu(dr[j][2] + bb.x), relu(dr[j][3] + bb.y));
        }
        __syncthreads();

        // ===== GEMM2: complex (K=128) + real (K=64), B from smem =====
        float e[4][4], er[2][4];
#pragma unroll
        for (int i = 0; i < 4; ++i) { e[i][0] = e[i][1] = e[i][2] = e[i][3] = 0.f; }
#pragma unroll
        for (int j = 0; j < 2; ++j) { er[j][0] = er[j][1] = er[j][2] = er[j][3] = 0.f; }
#pragma unroll
        for (int kt = 0; kt < 8; ++kt) {
            u32 a[4];
            ldsm4(a, h1b + (u32)(rowA * WPAD1 + kt * 16 + colA) * 2);
#pragma unroll
            for (int i = 0; i < 4; ++i) {
                u32 b[2];
                ldsm2(b, wb2b + (u32)((nc[i] + rowB) * WPAD2 + kt * 16 + colB) * 2);
                mma16816(e[i], a, b);
            }
        }
#pragma unroll
        for (int kt = 0; kt < 4; ++kt) {
            u32 a[4];
            ldsm4(a, h1b + (u32)(rowA * WPAD1 + 128 + kt * 16 + colA) * 2);
#pragma unroll
            for (int j = 0; j < 2; ++j) {
                u32 b[2];
                ldsm2(b, wb2b + (u32)((nr[j] + rowB) * WPAD2 + kt * 16 + colB) * 2);
                mma16816(er[j], a, b);
            }
        }

        // ===== Phase C: Koopman update (polynomial exp/sin/cos), y fp32 in regs =====
#pragma unroll
        for (int i = 0; i < 4; ++i) {
            int p = nc[i] + fc;
            float2 bb = *(const float2*)(sB2 + p);
            float* ee = e[i];
            float* yy = yc[i];
#pragma unroll
            for (int hh = 0; hh < 2; ++hh) {
                float mu = ee[2 * hh]     + bb.x;
                float om = ee[2 * hh + 1] + bb.y;
                float zm = DT * mu;
                float ex = 1.f + zm + zm * zm * (0.5f + zm * (1.f / 6.f));
                float zo = DT * om;
                float zo2 = zo * zo;
                float s = zo * (1.f - zo2 * (1.f / 6.f));
                float c = 1.f - zo2 * (0.5f - zo2 * (1.f / 24.f));
                float ye = yy[2 * hh], yo = yy[2 * hh + 1];
                float ne = ex * (c * ye - s * yo);
                float no = ex * (s * ye + c * yo);
                yy[2 * hh] = ne; yy[2 * hh + 1] = no;
            }
            yAw[(r0w * WPAD1 + p) >> 1]       = pkbf(yy[0], yy[1]);
            yAw[((r0w + 8) * WPAD1 + p) >> 1] = pkbf(yy[2], yy[3]);
            float* orow = outBase + (size_t)(r0w) * (TSTEPS * KD) + (size_t)t * KD + p;
            *(float2*)(orow) = make_float2(yy[0], yy[1]);
            *(float2*)(orow + (size_t)8 * TSTEPS * KD) = make_float2(yy[2], yy[3]);
        }
#pragma unroll
        for (int j = 0; j < 2; ++j) {
            int p = nr[j] + fc;
            float2 bb = *(const float2*)(sB2 + p);
            float* ee = er[j];
            float* yy = yr[j];
#pragma unroll
            for (int v = 0; v < 4; ++v) {
                float re = ee[v] + ((v & 1) ? bb.y : bb.x);
                float z = DT * re;
                float ex = 1.f + z + z * z * (0.5f + z * (1.f / 6.f));
                yy[v] *= ex;
            }
            yAw[(r0w * WPAD1 + p) >> 1]       = pkbf(yy[0], yy[1]);
            yAw[((r0w + 8) * WPAD1 + p) >> 1] = pkbf(yy[2], yy[3]);
            float* orow = outBase + (size_t)(r0w) * (TSTEPS * KD) + (size_t)t * KD + p;
            *(float2*)(orow) = make_float2(yy[0], yy[1]);
            *(float2*)(orow + (size_t)8 * TSTEPS * KD) = make_float2(yy[2], yy[3]);
        }
        __syncthreads();
    }
}

extern "C" void kernel_launch(void* const* d_in, const int* in_sizes, int n_in,
                              void* d_out, int out_size) {
    const float* x   = (const float*)d_in[0];
    const float* cW1 = (const float*)d_in[1];
    const float* cb1 = (const float*)d_in[2];
    const float* cW2 = (const float*)d_in[3];
    const float* cb2 = (const float*)d_in[4];
    const float* rW1 = (const float*)d_in[5];
    const float* rb1 = (const float*)d_in[6];
    const float* rW2 = (const float*)d_in[7];
    const float* rb2 = (const float*)d_in[8];
    float* out = (float*)d_out;

    cudaFuncSetAttribute(koopman_mma_kernel,
                         cudaFuncAttributeMaxDynamicSharedMemorySize, SMEM_BYTES);
    koopman_mma_kernel<<<CTAS, THREADS, SMEM_BYTES>>>(x, cW1, cb1, cW2, cb2,
                                                      rW1, rb1, rW2, rb2, out);
}